// round 1
// baseline (speedup 1.0000x reference)
#include <cuda_runtime.h>
#include <mma.h>
#include <cmath>
#include <cstdint>

using namespace nvcuda;

// Problem constants (fixed by the dataset)
constexpr int D_IN   = 1024;   // in_features
constexpr int NEXP   = 8;      // experts
constexpr int HID    = 4096;   // expert hidden
constexpr int TWOH   = 8192;   // 2*H (fc1 out)
constexpr int NTOK   = 4096;   // B*S tokens
constexpr int TOTALE = 8192;   // NTOK * top_k entries

// ---------------- static device scratch (no allocations allowed) -------------
__device__ int   g_counts[NEXP];
__device__ int   g_offsets[NEXP];
__device__ int   g_cursor[NEXP];
__device__ float g_probsum[NEXP];
__device__ int   g_topidx[NTOK * 2];
__device__ float g_topw[NTOK * 2];
__device__ int   g_tok[TOTALE];       // entry -> token id
__device__ float g_wt[TOTALE];        // entry -> combine weight
__device__ float g_h[(size_t)TOTALE * TWOH];   // fc1 output (gate|val), 256 MB
__device__ float g_act[(size_t)TOTALE * HID];  // silu(gate)*val, 128 MB

// ---------------- zero init (y + scratch counters) ---------------------------
__global__ void zero_kernel(float* __restrict__ out) {
    const int total4 = NTOK * D_IN / 4;
    float4* o4 = reinterpret_cast<float4*>(out);
    for (int i = blockIdx.x * blockDim.x + threadIdx.x; i < total4;
         i += gridDim.x * blockDim.x)
        o4[i] = make_float4(0.f, 0.f, 0.f, 0.f);
    if (blockIdx.x == 0 && threadIdx.x < NEXP) {
        g_counts[threadIdx.x]  = 0;
        g_cursor[threadIdx.x]  = 0;
        g_probsum[threadIdx.x] = 0.f;
    }
}

// ---------------- gating: logits, top-2, softmax weights, aux stats ----------
__global__ void gate_kernel(const float* __restrict__ x,
                            const float* __restrict__ Wg) {
    int gwarp = (blockIdx.x * blockDim.x + threadIdx.x) >> 5;
    int lane  = threadIdx.x & 31;
    if (gwarp >= NTOK) return;
    const float* xr = x + (size_t)gwarp * D_IN;

    float acc[NEXP];
#pragma unroll
    for (int e = 0; e < NEXP; e++) acc[e] = 0.f;

    for (int k = lane; k < D_IN; k += 32) {
        float xv = xr[k];
        const float4* w4 = reinterpret_cast<const float4*>(Wg + (size_t)k * NEXP);
        float4 a = w4[0];
        float4 b = w4[1];
        acc[0] += xv * a.x; acc[1] += xv * a.y;
        acc[2] += xv * a.z; acc[3] += xv * a.w;
        acc[4] += xv * b.x; acc[5] += xv * b.y;
        acc[6] += xv * b.z; acc[7] += xv * b.w;
    }
#pragma unroll
    for (int e = 0; e < NEXP; e++) {
#pragma unroll
        for (int off = 16; off > 0; off >>= 1)
            acc[e] += __shfl_xor_sync(0xffffffffu, acc[e], off);
    }
    if (lane == 0) {
        // top-2, ties -> lowest index (matches jax.lax.top_k)
        int i0 = 0; float v0 = acc[0];
#pragma unroll
        for (int e = 1; e < NEXP; e++)
            if (acc[e] > v0) { v0 = acc[e]; i0 = e; }
        int i1 = -1; float v1 = -3.4e38f;
#pragma unroll
        for (int e = 0; e < NEXP; e++)
            if (e != i0 && acc[e] > v1) { v1 = acc[e]; i1 = e; }
        float ex1 = expf(v1 - v0);
        float inv = 1.f / (1.f + ex1);
        g_topidx[2 * gwarp + 0] = i0;
        g_topidx[2 * gwarp + 1] = i1;
        g_topw[2 * gwarp + 0]   = inv;
        g_topw[2 * gwarp + 1]   = ex1 * inv;
        atomicAdd(&g_counts[i0], 1);
        atomicAdd(&g_counts[i1], 1);
        // full softmax for aux loss
        float s = 0.f;
        float p[NEXP];
#pragma unroll
        for (int e = 0; e < NEXP; e++) { p[e] = expf(acc[e] - v0); s += p[e]; }
        float rs = 1.f / s;
#pragma unroll
        for (int e = 0; e < NEXP; e++)
            atomicAdd(&g_probsum[e], p[e] * rs);
    }
}

// ---------------- offsets (scan) + aux loss ----------------------------------
__global__ void finalize_kernel(float* __restrict__ out) {
    if (threadIdx.x == 0 && blockIdx.x == 0) {
        int run = 0;
        float aux = 0.f;
#pragma unroll
        for (int e = 0; e < NEXP; e++) {
            g_offsets[e] = run;
            run += g_counts[e];
            aux += ((float)g_counts[e] / (float)NTOK) *
                   (g_probsum[e] / (float)NTOK);
        }
        out[(size_t)NTOK * D_IN] = aux * (float)NEXP;
    }
}

// ---------------- scatter tokens into per-expert packed lists ----------------
__global__ void scatter_kernel() {
    int n = blockIdx.x * blockDim.x + threadIdx.x;
    if (n >= NTOK) return;
#pragma unroll
    for (int k = 0; k < 2; k++) {
        int e = g_topidx[2 * n + k];
        int p = atomicAdd(&g_cursor[e], 1);
        int ent = g_offsets[e] + p;
        g_tok[ent] = n;
        g_wt[ent]  = g_topw[2 * n + k];
    }
}

// ---------------- GEMM tiles: 128x64, BK=32, tf32 wmma -----------------------
// As [128][36], Bs [64][36]; epilogue staging Cs reuses sm (128*64 floats).
constexpr int BM = 128, BN = 64, BK = 32, LDS = 36;

__global__ __launch_bounds__(256)
void gemm1_kernel(const float* __restrict__ x,
                  const float* __restrict__ W1,
                  const float* __restrict__ b1) {
    int e   = blockIdx.z;
    int cnt = g_counts[e];
    int m0  = blockIdx.y * BM;
    if (m0 >= cnt) return;
    int off = g_offsets[e];
    int n0  = blockIdx.x * BN;

    __shared__ __align__(256) float sm[BM * BN];   // 8192 floats
    __shared__ int stok[BM];
    float* As = sm;                 // 128*36 = 4608
    float* Bs = sm + BM * LDS;      // 64*36  = 2304 (ends at 6912)

    int tid = threadIdx.x;
    if (tid < BM) {
        int r = m0 + tid;
        stok[tid] = g_tok[off + (r < cnt ? r : 0)];
    }
    __syncthreads();

    wmma::fragment<wmma::accumulator, 16, 16, 8, float> c[2][2];
#pragma unroll
    for (int i = 0; i < 2; i++)
#pragma unroll
        for (int j = 0; j < 2; j++) wmma::fill_fragment(c[i][j], 0.f);

    const float* Bg = W1 + ((size_t)e * TWOH + n0) * D_IN;
    int warpId = tid >> 5;
    int wm = warpId >> 1;          // 0..3
    int wn = warpId & 1;           // 0..1
    int rr0 = tid >> 3, c4 = tid & 7;

    for (int kb = 0; kb < D_IN; kb += BK) {
#pragma unroll
        for (int i = 0; i < 4; i++) {
            int r = rr0 + i * 32;
            float4 v = *reinterpret_cast<const float4*>(
                x + (size_t)stok[r] * D_IN + kb + c4 * 4);
            float* dst = As + r * LDS + c4 * 4;
            dst[0] = wmma::__float_to_tf32(v.x);
            dst[1] = wmma::__float_to_tf32(v.y);
            dst[2] = wmma::__float_to_tf32(v.z);
            dst[3] = wmma::__float_to_tf32(v.w);
        }
#pragma unroll
        for (int i = 0; i < 2; i++) {
            int s = tid + i * 256;
            int r = s >> 3, cc = s & 7;
            float4 v = *reinterpret_cast<const float4*>(
                Bg + (size_t)r * D_IN + kb + cc * 4);
            float* dst = Bs + r * LDS + cc * 4;
            dst[0] = wmma::__float_to_tf32(v.x);
            dst[1] = wmma::__float_to_tf32(v.y);
            dst[2] = wmma::__float_to_tf32(v.z);
            dst[3] = wmma::__float_to_tf32(v.w);
        }
        __syncthreads();
#pragma unroll
        for (int kk = 0; kk < BK; kk += 8) {
            wmma::fragment<wmma::matrix_a, 16, 16, 8, wmma::precision::tf32,
                           wmma::row_major> a[2];
            wmma::fragment<wmma::matrix_b, 16, 16, 8, wmma::precision::tf32,
                           wmma::col_major> b[2];
            wmma::load_matrix_sync(a[0], As + (wm * 32 + 0)  * LDS + kk, LDS);
            wmma::load_matrix_sync(a[1], As + (wm * 32 + 16) * LDS + kk, LDS);
            wmma::load_matrix_sync(b[0], Bs + (wn * 32 + 0)  * LDS + kk, LDS);
            wmma::load_matrix_sync(b[1], Bs + (wn * 32 + 16) * LDS + kk, LDS);
#pragma unroll
            for (int i = 0; i < 2; i++)
#pragma unroll
                for (int j = 0; j < 2; j++)
                    wmma::mma_sync(c[i][j], a[i], b[j], c[i][j]);
        }
        __syncthreads();
    }

    float* Cs = sm;
#pragma unroll
    for (int i = 0; i < 2; i++)
#pragma unroll
        for (int j = 0; j < 2; j++)
            wmma::store_matrix_sync(Cs + (wm * 32 + i * 16) * BN + wn * 32 + j * 16,
                                    c[i][j], BN, wmma::mem_row_major);
    __syncthreads();
    for (int idx = tid; idx < BM * BN; idx += 256) {
        int r = idx >> 6, cc = idx & 63;
        if (m0 + r < cnt) {
            int col = n0 + cc;
            g_h[(size_t)(off + m0 + r) * TWOH + col] = Cs[idx] + b1[e * TWOH + col];
        }
    }
}

// ---------------- SiLU(gate)*val over packed entries -------------------------
__global__ void act_kernel() {
    const float4* h4 = reinterpret_cast<const float4*>(g_h);
    float4* a4 = reinterpret_cast<float4*>(g_act);
    const int total4 = TOTALE * (HID / 4);  // 8,388,608
    for (int i = blockIdx.x * blockDim.x + threadIdx.x; i < total4;
         i += gridDim.x * blockDim.x) {
        int ent = i >> 10;        // / (HID/4)
        int j   = i & 1023;
        float4 g = h4[(size_t)ent * (TWOH / 4) + j];
        float4 v = h4[(size_t)ent * (TWOH / 4) + (HID / 4) + j];
        float4 r;
        r.x = (g.x / (1.f + expf(-g.x))) * v.x;
        r.y = (g.y / (1.f + expf(-g.y))) * v.y;
        r.z = (g.z / (1.f + expf(-g.z))) * v.z;
        r.w = (g.w / (1.f + expf(-g.w))) * v.w;
        a4[i] = r;
    }
}

// ---------------- GEMM2: act @ fc2^T, weighted scatter-add into y ------------
__global__ __launch_bounds__(256)
void gemm2_kernel(const float* __restrict__ W2,
                  const float* __restrict__ b2,
                  float* __restrict__ out) {
    int e   = blockIdx.z;
    int cnt = g_counts[e];
    int m0  = blockIdx.y * BM;
    if (m0 >= cnt) return;
    int off = g_offsets[e];
    int n0  = blockIdx.x * BN;

    __shared__ __align__(256) float sm[BM * BN];
    __shared__ int   sent[BM];
    __shared__ int   etok[BM];
    __shared__ float ewt[BM];
    float* As = sm;
    float* Bs = sm + BM * LDS;

    int tid = threadIdx.x;
    if (tid < BM) {
        int r  = m0 + tid;
        int rc = (r < cnt) ? r : (cnt - 1);
        sent[tid] = off + rc;
        etok[tid] = g_tok[off + rc];
        ewt[tid]  = g_wt[off + rc];
    }
    __syncthreads();

    wmma::fragment<wmma::accumulator, 16, 16, 8, float> c[2][2];
#pragma unroll
    for (int i = 0; i < 2; i++)
#pragma unroll
        for (int j = 0; j < 2; j++) wmma::fill_fragment(c[i][j], 0.f);

    const float* Bg = W2 + ((size_t)e * D_IN + n0) * HID;
    int warpId = tid >> 5;
    int wm = warpId >> 1;
    int wn = warpId & 1;
    int rr0 = tid >> 3, c4 = tid & 7;

    for (int kb = 0; kb < HID; kb += BK) {
#pragma unroll
        for (int i = 0; i < 4; i++) {
            int r = rr0 + i * 32;
            float4 v = *reinterpret_cast<const float4*>(
                g_act + (size_t)sent[r] * HID + kb + c4 * 4);
            float* dst = As + r * LDS + c4 * 4;
            dst[0] = wmma::__float_to_tf32(v.x);
            dst[1] = wmma::__float_to_tf32(v.y);
            dst[2] = wmma::__float_to_tf32(v.z);
            dst[3] = wmma::__float_to_tf32(v.w);
        }
#pragma unroll
        for (int i = 0; i < 2; i++) {
            int s = tid + i * 256;
            int r = s >> 3, cc = s & 7;
            float4 v = *reinterpret_cast<const float4*>(
                Bg + (size_t)r * HID + kb + cc * 4);
            float* dst = Bs + r * LDS + cc * 4;
            dst[0] = wmma::__float_to_tf32(v.x);
            dst[1] = wmma::__float_to_tf32(v.y);
            dst[2] = wmma::__float_to_tf32(v.z);
            dst[3] = wmma::__float_to_tf32(v.w);
        }
        __syncthreads();
#pragma unroll
        for (int kk = 0; kk < BK; kk += 8) {
            wmma::fragment<wmma::matrix_a, 16, 16, 8, wmma::precision::tf32,
                           wmma::row_major> a[2];
            wmma::fragment<wmma::matrix_b, 16, 16, 8, wmma::precision::tf32,
                           wmma::col_major> b[2];
            wmma::load_matrix_sync(a[0], As + (wm * 32 + 0)  * LDS + kk, LDS);
            wmma::load_matrix_sync(a[1], As + (wm * 32 + 16) * LDS + kk, LDS);
            wmma::load_matrix_sync(b[0], Bs + (wn * 32 + 0)  * LDS + kk, LDS);
            wmma::load_matrix_sync(b[1], Bs + (wn * 32 + 16) * LDS + kk, LDS);
#pragma unroll
            for (int i = 0; i < 2; i++)
#pragma unroll
                for (int j = 0; j < 2; j++)
                    wmma::mma_sync(c[i][j], a[i], b[j], c[i][j]);
        }
        __syncthreads();
    }

    float* Cs = sm;
#pragma unroll
    for (int i = 0; i < 2; i++)
#pragma unroll
        for (int j = 0; j < 2; j++)
            wmma::store_matrix_sync(Cs + (wm * 32 + i * 16) * BN + wn * 32 + j * 16,
                                    c[i][j], BN, wmma::mem_row_major);
    __syncthreads();
    for (int idx = tid; idx < BM * BN; idx += 256) {
        int r = idx >> 6, cc = idx & 63;
        if (m0 + r < cnt) {
            float val = Cs[idx] + b2[e * D_IN + n0 + cc];
            atomicAdd(&out[(size_t)etok[r] * D_IN + n0 + cc], ewt[r] * val);
        }
    }
}

// ---------------- launch ------------------------------------------------------
extern "C" void kernel_launch(void* const* d_in, const int* in_sizes, int n_in,
                              void* d_out, int out_size) {
    const float* x  = (const float*)d_in[0];
    const float* Wg = (const float*)d_in[1];
    const float* W1 = (const float*)d_in[2];
    const float* b1 = (const float*)d_in[3];
    const float* W2 = (const float*)d_in[4];
    const float* b2 = (const float*)d_in[5];
    float* out = (float*)d_out;

    zero_kernel<<<1024, 256>>>(out);
    gate_kernel<<<NTOK / 8, 256>>>(x, Wg);
    finalize_kernel<<<1, 1>>>(out);
    scatter_kernel<<<NTOK / 256, 256>>>();

    dim3 g1(TWOH / BN, NTOK / BM, NEXP);  // (128, 32, 8)
    gemm1_kernel<<<g1, 256>>>(x, W1, b1);

    act_kernel<<<4096, 256>>>();

    dim3 g2(D_IN / BN, NTOK / BM, NEXP);  // (16, 32, 8)
    gemm2_kernel<<<g2, 256>>>(W2, b2, out);
}

// round 2
// speedup vs baseline: 2.9116x; 2.9116x over previous
#include <cuda_runtime.h>
#include <cuda_fp16.h>
#include <mma.h>
#include <cmath>
#include <cstdint>

using namespace nvcuda;

// Problem constants (fixed by the dataset)
constexpr int D_IN   = 1024;
constexpr int NEXP   = 8;
constexpr int HID    = 4096;
constexpr int TWOH   = 8192;
constexpr int NTOK   = 4096;
constexpr int TOTALE = 8192;

// ---------------- static device scratch ----------------
__device__ int   g_counts[NEXP];
__device__ int   g_offsets[NEXP];
__device__ int   g_cursor[NEXP];
__device__ float g_probsum[NEXP];
__device__ int   g_topidx[NTOK * 2];
__device__ float g_topw[NTOK * 2];
__device__ int   g_tok[TOTALE];
__device__ float g_wt[TOTALE];
__device__ __half g_xh[(size_t)NTOK * D_IN];          // 8 MB
__device__ __half g_W1h[(size_t)NEXP * TWOH * D_IN];  // 128 MB
__device__ __half g_W2h[(size_t)NEXP * D_IN * HID];   // 64 MB
__device__ __half g_acth[(size_t)TOTALE * HID];       // 64 MB

// ---------------- cp.async helpers ----------------
__device__ __forceinline__ void cp16(void* s, const void* g) {
    unsigned sa = (unsigned)__cvta_generic_to_shared(s);
    asm volatile("cp.async.cg.shared.global [%0], [%1], 16;\n" :: "r"(sa), "l"(g));
}
__device__ __forceinline__ void cp_commit() {
    asm volatile("cp.async.commit_group;\n");
}
template <int N>
__device__ __forceinline__ void cp_wait() {
    asm volatile("cp.async.wait_group %0;\n" :: "n"(N));
}

// ---------------- zero init ----------------
__global__ void zero_kernel(float* __restrict__ out) {
    const int total4 = NTOK * D_IN / 4;
    float4* o4 = reinterpret_cast<float4*>(out);
    for (int i = blockIdx.x * blockDim.x + threadIdx.x; i < total4;
         i += gridDim.x * blockDim.x)
        o4[i] = make_float4(0.f, 0.f, 0.f, 0.f);
    if (blockIdx.x == 0 && threadIdx.x < NEXP) {
        g_counts[threadIdx.x]  = 0;
        g_cursor[threadIdx.x]  = 0;
        g_probsum[threadIdx.x] = 0.f;
    }
}

// ---------------- fp32 -> fp16 convert ----------------
__global__ void f2h_kernel(const float* __restrict__ src,
                           __half* __restrict__ dst, int n4) {
    for (int i = blockIdx.x * blockDim.x + threadIdx.x; i < n4;
         i += gridDim.x * blockDim.x) {
        float4 v = reinterpret_cast<const float4*>(src)[i];
        __half2 lo = __floats2half2_rn(v.x, v.y);
        __half2 hi = __floats2half2_rn(v.z, v.w);
        reinterpret_cast<__half2*>(dst)[2 * i + 0] = lo;
        reinterpret_cast<__half2*>(dst)[2 * i + 1] = hi;
    }
}

// ---------------- gating ----------------
__global__ void gate_kernel(const float* __restrict__ x,
                            const float* __restrict__ Wg) {
    int gwarp = (blockIdx.x * blockDim.x + threadIdx.x) >> 5;
    int lane  = threadIdx.x & 31;
    if (gwarp >= NTOK) return;
    const float* xr = x + (size_t)gwarp * D_IN;

    float acc[NEXP];
#pragma unroll
    for (int e = 0; e < NEXP; e++) acc[e] = 0.f;

    for (int k = lane; k < D_IN; k += 32) {
        float xv = xr[k];
        const float4* w4 = reinterpret_cast<const float4*>(Wg + (size_t)k * NEXP);
        float4 a = w4[0];
        float4 b = w4[1];
        acc[0] += xv * a.x; acc[1] += xv * a.y;
        acc[2] += xv * a.z; acc[3] += xv * a.w;
        acc[4] += xv * b.x; acc[5] += xv * b.y;
        acc[6] += xv * b.z; acc[7] += xv * b.w;
    }
#pragma unroll
    for (int e = 0; e < NEXP; e++) {
#pragma unroll
        for (int off = 16; off > 0; off >>= 1)
            acc[e] += __shfl_xor_sync(0xffffffffu, acc[e], off);
    }
    if (lane == 0) {
        int i0 = 0; float v0 = acc[0];
#pragma unroll
        for (int e = 1; e < NEXP; e++)
            if (acc[e] > v0) { v0 = acc[e]; i0 = e; }
        int i1 = -1; float v1 = -3.4e38f;
#pragma unroll
        for (int e = 0; e < NEXP; e++)
            if (e != i0 && acc[e] > v1) { v1 = acc[e]; i1 = e; }
        float ex1 = expf(v1 - v0);
        float inv = 1.f / (1.f + ex1);
        g_topidx[2 * gwarp + 0] = i0;
        g_topidx[2 * gwarp + 1] = i1;
        g_topw[2 * gwarp + 0]   = inv;
        g_topw[2 * gwarp + 1]   = ex1 * inv;
        atomicAdd(&g_counts[i0], 1);
        atomicAdd(&g_counts[i1], 1);
        float s = 0.f;
        float p[NEXP];
#pragma unroll
        for (int e = 0; e < NEXP; e++) { p[e] = expf(acc[e] - v0); s += p[e]; }
        float rs = 1.f / s;
#pragma unroll
        for (int e = 0; e < NEXP; e++)
            atomicAdd(&g_probsum[e], p[e] * rs);
    }
}

// ---------------- scan + aux ----------------
__global__ void finalize_kernel(float* __restrict__ out) {
    if (threadIdx.x == 0 && blockIdx.x == 0) {
        int run = 0;
        float aux = 0.f;
#pragma unroll
        for (int e = 0; e < NEXP; e++) {
            g_offsets[e] = run;
            run += g_counts[e];
            aux += ((float)g_counts[e] / (float)NTOK) *
                   (g_probsum[e] / (float)NTOK);
        }
        out[(size_t)NTOK * D_IN] = aux * (float)NEXP;
    }
}

// ---------------- scatter ----------------
__global__ void scatter_kernel() {
    int n = blockIdx.x * blockDim.x + threadIdx.x;
    if (n >= NTOK) return;
#pragma unroll
    for (int k = 0; k < 2; k++) {
        int e = g_topidx[2 * n + k];
        int p = atomicAdd(&g_cursor[e], 1);
        int ent = g_offsets[e] + p;
        g_tok[ent] = n;
        g_wt[ent]  = g_topw[2 * n + k];
    }
}

// ---------------- GEMM config ----------------
constexpr int BM = 128, BN = 64, BK = 32, LDSH = 40;  // halves, 40*2=80B rows (16B aligned)
constexpr int STAGE_H = BM * LDSH;                     // 5120 halves per stage

// ============ GEMM1 fused with SiLU-gate: act = silu(x@Wg^T) * (x@Wv^T) ============
// Block computes 128 rows x (64 gate + 64 val) cols, writes 128x64 fp16 act tile.
__global__ __launch_bounds__(256)
void gemm1_kernel(const float* __restrict__ b1) {
    int e   = blockIdx.z;
    int cnt = g_counts[e];
    int m0  = blockIdx.y * BM;
    if (m0 >= cnt) return;
    int off = g_offsets[e];
    int n0  = blockIdx.x * BN;

    __shared__ __align__(16) unsigned char smraw[40960];
    __shared__ int stok[BM];
    __half* As = (__half*)smraw;                  // [2][5120]
    __half* Bs = (__half*)(smraw + 20480);        // [2][5120]
    float*  Cf = (float*)smraw;                   // epilogue: [128][68] = 34816 B

    int tid = threadIdx.x;
    if (tid < BM) {
        int r = m0 + tid;
        stok[tid] = g_tok[off + (r < cnt ? r : 0)];
    }
    __syncthreads();

    // per-thread fixed load mapping: 16B chunk, rows rA and rA+64
    int rA = tid >> 2, cc = tid & 3;
    const __half* aS0 = g_xh + (size_t)stok[rA] * D_IN + cc * 8;
    const __half* aS1 = g_xh + (size_t)stok[rA + 64] * D_IN + cc * 8;
    const __half* bS0 = g_W1h + ((size_t)e * TWOH + n0 + rA) * D_IN + cc * 8;        // gate rows
    const __half* bS1 = g_W1h + ((size_t)e * TWOH + HID + n0 + rA) * D_IN + cc * 8;  // val rows
    int dA0 = rA * LDSH + cc * 8;
    int dA1 = (rA + 64) * LDSH + cc * 8;

    wmma::fragment<wmma::accumulator, 16, 16, 16, float> cg[2][2], cv[2][2];
#pragma unroll
    for (int i = 0; i < 2; i++)
#pragma unroll
        for (int j = 0; j < 2; j++) {
            wmma::fill_fragment(cg[i][j], 0.f);
            wmma::fill_fragment(cv[i][j], 0.f);
        }

    int warp = tid >> 5, wm = warp >> 1, wn = warp & 1;

    // prologue
    {
        cp16(As + dA0, aS0); cp16(As + dA1, aS1);
        cp16(Bs + dA0, bS0); cp16(Bs + dA1, bS1);
        cp_commit();
    }
    const int nk = D_IN / BK;  // 32
    for (int k = 0; k < nk; k++) {
        if (k + 1 < nk) {
            int buf = (k + 1) & 1;
            int kb  = (k + 1) * BK;
            cp16(As + buf * STAGE_H + dA0, aS0 + kb);
            cp16(As + buf * STAGE_H + dA1, aS1 + kb);
            cp16(Bs + buf * STAGE_H + dA0, bS0 + kb);
            cp16(Bs + buf * STAGE_H + dA1, bS1 + kb);
            cp_commit();
            cp_wait<1>();
        } else {
            cp_wait<0>();
        }
        __syncthreads();
        const __half* a = As + (k & 1) * STAGE_H;
        const __half* b = Bs + (k & 1) * STAGE_H;
#pragma unroll
        for (int kk = 0; kk < BK; kk += 16) {
            wmma::fragment<wmma::matrix_a, 16, 16, 16, __half, wmma::row_major> af[2];
            wmma::fragment<wmma::matrix_b, 16, 16, 16, __half, wmma::col_major> bg[2], bv[2];
            wmma::load_matrix_sync(af[0], a + (wm * 32 + 0)  * LDSH + kk, LDSH);
            wmma::load_matrix_sync(af[1], a + (wm * 32 + 16) * LDSH + kk, LDSH);
            wmma::load_matrix_sync(bg[0], b + (wn * 32 + 0)  * LDSH + kk, LDSH);
            wmma::load_matrix_sync(bg[1], b + (wn * 32 + 16) * LDSH + kk, LDSH);
            wmma::load_matrix_sync(bv[0], b + (64 + wn * 32 + 0)  * LDSH + kk, LDSH);
            wmma::load_matrix_sync(bv[1], b + (64 + wn * 32 + 16) * LDSH + kk, LDSH);
#pragma unroll
            for (int i = 0; i < 2; i++)
#pragma unroll
                for (int j = 0; j < 2; j++) {
                    wmma::mma_sync(cg[i][j], af[i], bg[j], cg[i][j]);
                    wmma::mma_sync(cv[i][j], af[i], bv[j], cv[i][j]);
                }
        }
        __syncthreads();
    }

    // epilogue: gate pass -> silu held in regs -> val pass -> fused write
#pragma unroll
    for (int i = 0; i < 2; i++)
#pragma unroll
        for (int j = 0; j < 2; j++)
            wmma::store_matrix_sync(Cf + (wm * 32 + i * 16) * 68 + wn * 32 + j * 16,
                                    cg[i][j], 68, wmma::mem_row_major);
    __syncthreads();
    float sg[32];
#pragma unroll
    for (int t = 0; t < 32; t++) {
        int lin = t * 256 + tid;
        int r = lin >> 6, c2 = lin & 63;
        float gv = Cf[r * 68 + c2] + b1[e * TWOH + n0 + c2];
        sg[t] = gv / (1.f + expf(-gv));
    }
    __syncthreads();
#pragma unroll
    for (int i = 0; i < 2; i++)
#pragma unroll
        for (int j = 0; j < 2; j++)
            wmma::store_matrix_sync(Cf + (wm * 32 + i * 16) * 68 + wn * 32 + j * 16,
                                    cv[i][j], 68, wmma::mem_row_major);
    __syncthreads();
#pragma unroll
    for (int t = 0; t < 32; t++) {
        int lin = t * 256 + tid;
        int r = lin >> 6, c2 = lin & 63;
        if (m0 + r < cnt) {
            float vv = Cf[r * 68 + c2] + b1[e * TWOH + HID + n0 + c2];
            g_acth[(size_t)(off + m0 + r) * HID + n0 + c2] =
                __float2half(sg[t] * vv);
        }
    }
}

// ============ GEMM2: act(fp16) @ fc2^T + weighted scatter-add ============
__global__ __launch_bounds__(256)
void gemm2_kernel(const float* __restrict__ b2, float* __restrict__ out) {
    int e   = blockIdx.z;
    int cnt = g_counts[e];
    int m0  = blockIdx.y * BM;
    if (m0 >= cnt) return;
    int off = g_offsets[e];
    int n0  = blockIdx.x * BN;

    __shared__ __align__(16) unsigned char smraw[40960];
    __shared__ int   etok[BM];
    __shared__ float ewt[BM];
    __half* As = (__half*)smraw;                  // [2][5120]
    __half* Bs = (__half*)(smraw + 20480);        // [2][2560]
    float*  Cf = (float*)smraw;                   // epilogue [128][68]

    int tid = threadIdx.x;
    if (tid < BM) {
        int r  = m0 + tid;
        int rc = (r < cnt) ? r : (cnt - 1);
        etok[tid] = g_tok[off + rc];
        ewt[tid]  = g_wt[off + rc];
    }
    __syncthreads();

    int rA = tid >> 2, cc = tid & 3;
    int rc0 = (m0 + rA      < cnt) ? (m0 + rA)      : (cnt - 1);
    int rc1 = (m0 + rA + 64 < cnt) ? (m0 + rA + 64) : (cnt - 1);
    const __half* aS0 = g_acth + (size_t)(off + rc0) * HID + cc * 8;
    const __half* aS1 = g_acth + (size_t)(off + rc1) * HID + cc * 8;
    const __half* bS0 = g_W2h + ((size_t)e * D_IN + n0 + rA) * HID + cc * 8;
    int dA0 = rA * LDSH + cc * 8;
    int dA1 = (rA + 64) * LDSH + cc * 8;
    int dB  = rA * LDSH + cc * 8;

    wmma::fragment<wmma::accumulator, 16, 16, 16, float> c[2][2];
#pragma unroll
    for (int i = 0; i < 2; i++)
#pragma unroll
        for (int j = 0; j < 2; j++) wmma::fill_fragment(c[i][j], 0.f);

    int warp = tid >> 5, wm = warp >> 1, wn = warp & 1;

    {
        cp16(As + dA0, aS0); cp16(As + dA1, aS1);
        cp16(Bs + dB, bS0);
        cp_commit();
    }
    const int nk = HID / BK;  // 128
    for (int k = 0; k < nk; k++) {
        if (k + 1 < nk) {
            int buf = (k + 1) & 1;
            int kb  = (k + 1) * BK;
            cp16(As + buf * STAGE_H + dA0, aS0 + kb);
            cp16(As + buf * STAGE_H + dA1, aS1 + kb);
            cp16(Bs + buf * 2560 + dB, bS0 + kb);
            cp_commit();
            cp_wait<1>();
        } else {
            cp_wait<0>();
        }
        __syncthreads();
        const __half* a = As + (k & 1) * STAGE_H;
        const __half* b = Bs + (k & 1) * 2560;
#pragma unroll
        for (int kk = 0; kk < BK; kk += 16) {
            wmma::fragment<wmma::matrix_a, 16, 16, 16, __half, wmma::row_major> af[2];
            wmma::fragment<wmma::matrix_b, 16, 16, 16, __half, wmma::col_major> bf[2];
            wmma::load_matrix_sync(af[0], a + (wm * 32 + 0)  * LDSH + kk, LDSH);
            wmma::load_matrix_sync(af[1], a + (wm * 32 + 16) * LDSH + kk, LDSH);
            wmma::load_matrix_sync(bf[0], b + (wn * 32 + 0)  * LDSH + kk, LDSH);
            wmma::load_matrix_sync(bf[1], b + (wn * 32 + 16) * LDSH + kk, LDSH);
#pragma unroll
            for (int i = 0; i < 2; i++)
#pragma unroll
                for (int j = 0; j < 2; j++)
                    wmma::mma_sync(c[i][j], af[i], bf[j], c[i][j]);
        }
        __syncthreads();
    }

#pragma unroll
    for (int i = 0; i < 2; i++)
#pragma unroll
        for (int j = 0; j < 2; j++)
            wmma::store_matrix_sync(Cf + (wm * 32 + i * 16) * 68 + wn * 32 + j * 16,
                                    c[i][j], 68, wmma::mem_row_major);
    __syncthreads();
#pragma unroll
    for (int t = 0; t < 32; t++) {
        int lin = t * 256 + tid;
        int r = lin >> 6, c2 = lin & 63;
        if (m0 + r < cnt) {
            float val = Cf[r * 68 + c2] + b2[e * D_IN + n0 + c2];
            atomicAdd(&out[(size_t)etok[r] * D_IN + n0 + c2], ewt[r] * val);
        }
    }
}

// ---------------- launch ----------------
extern "C" void kernel_launch(void* const* d_in, const int* in_sizes, int n_in,
                              void* d_out, int out_size) {
    const float* x  = (const float*)d_in[0];
    const float* Wg = (const float*)d_in[1];
    const float* W1 = (const float*)d_in[2];
    const float* b1 = (const float*)d_in[3];
    const float* W2 = (const float*)d_in[4];
    const float* b2 = (const float*)d_in[5];
    float* out = (float*)d_out;

    zero_kernel<<<1024, 256>>>(out);

    __half* xh;  cudaGetSymbolAddress((void**)&xh,  g_xh);
    __half* w1h; cudaGetSymbolAddress((void**)&w1h, g_W1h);
    __half* w2h; cudaGetSymbolAddress((void**)&w2h, g_W2h);
    f2h_kernel<<<2048, 256>>>(x,  xh,  NTOK * D_IN / 4);
    f2h_kernel<<<8192, 256>>>(W1, w1h, NEXP * TWOH * D_IN / 4);
    f2h_kernel<<<8192, 256>>>(W2, w2h, NEXP * D_IN * HID / 4);

    gate_kernel<<<NTOK / 8, 256>>>(x, Wg);
    finalize_kernel<<<1, 1>>>(out);
    scatter_kernel<<<NTOK / 256, 256>>>();

    dim3 g1(HID / BN, NTOK / BM, NEXP);   // (64, 32, 8)
    gemm1_kernel<<<g1, 256>>>(b1);

    dim3 g2(D_IN / BN, NTOK / BM, NEXP);  // (16, 32, 8)
    gemm2_kernel<<<g2, 256>>>(b2, out);
}